// round 8
// baseline (speedup 1.0000x reference)
#include <cuda_runtime.h>
#include <math.h>

// Problem dims (per reference: V,E,H,C = 50000,300,512,3; B=64,P=128,Th=64)
#define kB   64
#define kE   300
#define kH   512
#define kH4  2048
#define kPL  128
#define kHL  64
#define kC   3
#define kV   50000

// ---------------- scratch (device globals; no allocation allowed) ----------
__device__ __align__(16) float g_GXp[(size_t)kPL*kB*kH4];   // [t][b][4H]
__device__ __align__(16) float g_GXh[(size_t)kHL*kB*kH4];   // [t][b][4H]
__device__ __align__(16) float g_outp[(size_t)kB*kPL*kH];   // [b][p][h]
__device__ __align__(16) float g_outh[(size_t)kB*kHL*kH];   // [b][t][h]
__device__ __align__(16) float g_a1  [(size_t)kB*kPL*kH];   // [b][p][h]
__device__ __align__(16) float g_h[2][kB*kH];
__device__ __align__(16) float g_c[2][kB*kH];
__device__ __align__(16) float g_r  [kB*kH];
__device__ __align__(16) float g_a2 [kB*kH];
__device__ __align__(16) float g_rt [kB*kH];
__device__ __align__(16) float g_rep[kB*kH];

// ---------------- math helpers ----------------
__device__ __forceinline__ float fsigmoid(float x) {
    return __fdividef(1.0f, 1.0f + __expf(-x));
}
__device__ __forceinline__ float ftanh(float x) {
    return 1.0f - __fdividef(2.0f, __expf(2.0f * x) + 1.0f);
}

// ---------------- utility kernels ----------------
__global__ void zero_init() {
    int i = blockIdx.x * blockDim.x + threadIdx.x;
    if (i < kB * kH) { g_h[0][i] = 0.f; g_c[0][i] = 0.f; g_r[i] = 0.f; }
}
__global__ void zero_h0() {
    int i = blockIdx.x * blockDim.x + threadIdx.x;
    if (i < kB * kH) g_h[0][i] = 0.f;
}
__global__ void zero_out_k(float* out, int n) {
    int i = blockIdx.x * blockDim.x + threadIdx.x;
    if (i < n) out[i] = 0.f;
}

// ---------------- GEMM: C[m][n] = bias(n) + sum_k A(m,k) * W[n][k] --------
// mode 0: A = emb[premise gather] (K=300) -> g_GXp  (M = kPL*kB, N = 2048)
// mode 1: A = emb[hyp gather]     (K=300) -> g_GXh  (M = kHL*kB, N = 2048)
// mode 2: A = g_outp              (K=512) -> g_a1   (M = kB*kPL, N = 512)
// blockDim (32,32); grid (N/32, M/32). One output per thread. K bounds-guarded.
__global__ void __launch_bounds__(1024) gemm_simple(
    int mode, const float* __restrict__ emb, const int* __restrict__ tok,
    const float* __restrict__ W, const float* __restrict__ bias1,
    const float* __restrict__ bias2, int N, int K, int T)
{
    float* Cout = (mode == 0) ? g_GXp : (mode == 1) ? g_GXh : g_a1;

    __shared__ float As[32][33];
    __shared__ float Ws[32][33];

    int tx = threadIdx.x;            // 0..31
    int ty = threadIdx.y;            // 0..31
    int m  = blockIdx.y * 32 + ty;   // output row (this thread also loads A row m)
    int n  = blockIdx.x * 32 + tx;   // output col

    const float* arow;
    if (mode <= 1) {
        int t = m >> 6;              // m / kB
        int b = m & 63;              // m % kB
        int tk = tok[b * T + t];
        tk = (tk < 0) ? 0 : ((tk >= kV) ? (kV - 1) : tk);
        arow = emb + (size_t)tk * K;     // E = 300 row stride
    } else {
        arow = g_outp + (size_t)m * K;   // K = 512
    }
    const float* wrow = W + (size_t)(blockIdx.x * 32 + ty) * K;

    float acc = 0.f;
    for (int k0 = 0; k0 < K; k0 += 32) {
        As[ty][tx] = (k0 + tx < K) ? arow[k0 + tx] : 0.f;
        Ws[ty][tx] = (k0 + tx < K) ? wrow[k0 + tx] : 0.f;
        __syncthreads();
#pragma unroll
        for (int kk = 0; kk < 32; kk++)
            acc += As[ty][kk] * Ws[tx][kk];
        __syncthreads();
    }
    float v = acc;
    if (bias1) v += bias1[n];
    if (bias2) v += bias2[n];
    Cout[(size_t)m * N + n] = v;
}

// ---------------- fused LSTM step ----------------
// grid 256 x 128 threads. thread -> (b = tid&63, j = blk*2 + tid>>6). K = H = 512.
__global__ void __launch_bounds__(128) lstm_step(
    int phase, int t, const float* __restrict__ Whh)
{
    const float* GX;  float* outbuf;  int T;
    if (phase == 0) { GX = g_GXp + (size_t)t * kB * kH4; outbuf = g_outp; T = kPL; }
    else            { GX = g_GXh + (size_t)t * kB * kH4; outbuf = g_outh; T = kHL; }
    const float* h_in = g_h[t & 1];
    const float* c_in = g_c[t & 1];
    float* h_out = g_h[(t + 1) & 1];
    float* c_out = g_c[(t + 1) & 1];

    __shared__ float hs[64][33];
    int tid = threadIdx.x;
    int b = tid & 63;
    int j = (blockIdx.x << 1) + (tid >> 6);

    float a0 = 0.f, a1 = 0.f, a2 = 0.f, a3 = 0.f;
    const float* w0p = Whh + (size_t)(j) * kH;
    const float* w1p = Whh + (size_t)(512 + j) * kH;
    const float* w2p = Whh + (size_t)(1024 + j) * kH;
    const float* w3p = Whh + (size_t)(1536 + j) * kH;

    for (int k0 = 0; k0 < kH; k0 += 32) {
#pragma unroll
        for (int i = 0; i < 4; i++) {
            int l = i * 128 + tid;         // 0..511
            int row = l >> 3;              // 0..63
            int c4 = (l & 7) << 2;         // 0..28
            float4 v = *(const float4*)(h_in + row * kH + k0 + c4);
            hs[row][c4 + 0] = v.x; hs[row][c4 + 1] = v.y;
            hs[row][c4 + 2] = v.z; hs[row][c4 + 3] = v.w;
        }
        __syncthreads();
#pragma unroll
        for (int k = 0; k < 32; k += 4) {
            float4 w0 = *(const float4*)(w0p + k0 + k);
            float4 w1 = *(const float4*)(w1p + k0 + k);
            float4 w2 = *(const float4*)(w2p + k0 + k);
            float4 w3 = *(const float4*)(w3p + k0 + k);
            float h0v = hs[b][k], h1v = hs[b][k + 1], h2v = hs[b][k + 2], h3v = hs[b][k + 3];
            a0 += h0v * w0.x + h1v * w0.y + h2v * w0.z + h3v * w0.w;
            a1 += h0v * w1.x + h1v * w1.y + h2v * w1.z + h3v * w1.w;
            a2 += h0v * w2.x + h1v * w2.y + h2v * w2.z + h3v * w2.w;
            a3 += h0v * w3.x + h1v * w3.y + h2v * w3.z + h3v * w3.w;
        }
        __syncthreads();
    }
    float gi = GX[b * kH4 + j] + a0;
    float gf = GX[b * kH4 + 512 + j] + a1;
    float gg = GX[b * kH4 + 1024 + j] + a2;
    float go = GX[b * kH4 + 1536 + j] + a3;
    float c = fsigmoid(gf) * c_in[b * kH + j] + fsigmoid(gi) * ftanh(gg);
    float h = fsigmoid(go) * ftanh(c);
    c_out[b * kH + j] = c;
    h_out[b * kH + j] = h;
    outbuf[((size_t)b * T + t) * kH + j] = h;
}

// ---------------- attention precompute: a2 = qW_h^T + rW_r^T, rt = tanh(rW_t^T)
__global__ void __launch_bounds__(128) att_pre(
    int t, const float* __restrict__ Wh, const float* __restrict__ Wr,
    const float* __restrict__ Wt)
{
    __shared__ float qs[64][33];
    __shared__ float rs[64][33];
    int tid = threadIdx.x;
    int b = tid & 63;
    int j = (blockIdx.x << 1) + (tid >> 6);

    float ah = 0.f, ar = 0.f, at = 0.f;
    const float* whp = Wh + (size_t)j * kH;
    const float* wrp = Wr + (size_t)j * kH;
    const float* wtp = Wt + (size_t)j * kH;

    for (int k0 = 0; k0 < kH; k0 += 32) {
#pragma unroll
        for (int i = 0; i < 4; i++) {
            int l = i * 128 + tid;
            int row = l >> 3;
            int c4 = (l & 7) << 2;
            float4 qv = *(const float4*)(g_outh + ((size_t)row * kHL + t) * kH + k0 + c4);
            float4 rv = *(const float4*)(g_r + row * kH + k0 + c4);
            qs[row][c4 + 0] = qv.x; qs[row][c4 + 1] = qv.y;
            qs[row][c4 + 2] = qv.z; qs[row][c4 + 3] = qv.w;
            rs[row][c4 + 0] = rv.x; rs[row][c4 + 1] = rv.y;
            rs[row][c4 + 2] = rv.z; rs[row][c4 + 3] = rv.w;
        }
        __syncthreads();
#pragma unroll
        for (int k = 0; k < 32; k += 4) {
            float4 wh = *(const float4*)(whp + k0 + k);
            float4 wr = *(const float4*)(wrp + k0 + k);
            float4 wt = *(const float4*)(wtp + k0 + k);
            float q0 = qs[b][k], q1 = qs[b][k + 1], q2 = qs[b][k + 2], q3 = qs[b][k + 3];
            float r0 = rs[b][k], r1 = rs[b][k + 1], r2 = rs[b][k + 2], r3 = rs[b][k + 3];
            ah += q0 * wh.x + q1 * wh.y + q2 * wh.z + q3 * wh.w;
            ar += r0 * wr.x + r1 * wr.y + r2 * wr.z + r3 * wr.w;
            at += r0 * wt.x + r1 * wt.y + r2 * wt.z + r3 * wt.w;
        }
        __syncthreads();
    }
    g_a2[b * kH + j] = ah + ar;
    g_rt[b * kH + j] = ftanh(at);
}

// ---------------- attention scores + softmax + r update (one block per b) --
__global__ void __launch_bounds__(512) att_update(const float* __restrict__ w_att)
{
    int b = blockIdx.x;
    int tid = threadIdx.x;
    __shared__ float a2s[512];
    __shared__ float wvs[512];
    __shared__ float ss[128];
    __shared__ float red[16];

    a2s[tid] = g_a2[b * kH + tid];
    wvs[tid] = w_att[tid];
    __syncthreads();

    int p = tid >> 2, sub = tid & 3;
    const float* a1p = g_a1 + ((size_t)b * kPL + p) * kH + (sub << 7);
    const float* a2p = a2s + (sub << 7);
    const float* wvp = wvs + (sub << 7);
    float part = 0.f;
#pragma unroll 4
    for (int k = 0; k < 128; k++)
        part += wvp[k] * ftanh(a1p[k] + a2p[k]);
    part += __shfl_xor_sync(0xffffffffu, part, 1);
    part += __shfl_xor_sync(0xffffffffu, part, 2);
    if (sub == 0) ss[p] = part;
    __syncthreads();

    float v = (tid < 128) ? ss[tid] : -3.4e38f;
#pragma unroll
    for (int o = 16; o; o >>= 1) v = fmaxf(v, __shfl_xor_sync(0xffffffffu, v, o));
    if ((tid & 31) == 0) red[tid >> 5] = v;
    __syncthreads();
    float mx = red[0];
#pragma unroll
    for (int w = 1; w < 16; w++) mx = fmaxf(mx, red[w]);
    __syncthreads();

    float e = 0.f;
    if (tid < 128) e = __expf(ss[tid] - mx);
    float sv = e;
#pragma unroll
    for (int o = 16; o; o >>= 1) sv += __shfl_xor_sync(0xffffffffu, sv, o);
    if ((tid & 31) == 0) red[tid >> 5] = sv;
    __syncthreads();
    float tot = 0.f;
#pragma unroll
    for (int w = 0; w < 16; w++) tot += red[w];
    if (tid < 128) ss[tid] = __fdividef(e, tot);
    __syncthreads();

    float acc = g_rt[b * kH + tid];
    const float* op = g_outp + (size_t)b * kPL * kH + tid;
#pragma unroll 4
    for (int p2 = 0; p2 < kPL; p2++)
        acc += op[(size_t)p2 * kH] * ss[p2];
    g_r[b * kH + tid] = acc;
}

// ---------------- final: rep = tanh(r@fc1^T + b1 + hn@fc2^T + b2) ----------
__global__ void __launch_bounds__(128) final_rep(
    const float* __restrict__ w1, const float* __restrict__ b1,
    const float* __restrict__ w2, const float* __restrict__ b2)
{
    __shared__ float rs[64][33];
    __shared__ float hs[64][33];
    int tid = threadIdx.x;
    int b = tid & 63;
    int j = (blockIdx.x << 1) + (tid >> 6);
    const float* hn = g_h[0];

    float acc1 = 0.f, acc2 = 0.f;
    const float* w1p = w1 + (size_t)j * kH;
    const float* w2p = w2 + (size_t)j * kH;

    for (int k0 = 0; k0 < kH; k0 += 32) {
#pragma unroll
        for (int i = 0; i < 4; i++) {
            int l = i * 128 + tid;
            int row = l >> 3;
            int c4 = (l & 7) << 2;
            float4 rv = *(const float4*)(g_r + row * kH + k0 + c4);
            float4 hv = *(const float4*)(hn + row * kH + k0 + c4);
            rs[row][c4 + 0] = rv.x; rs[row][c4 + 1] = rv.y;
            rs[row][c4 + 2] = rv.z; rs[row][c4 + 3] = rv.w;
            hs[row][c4 + 0] = hv.x; hs[row][c4 + 1] = hv.y;
            hs[row][c4 + 2] = hv.z; hs[row][c4 + 3] = hv.w;
        }
        __syncthreads();
#pragma unroll
        for (int k = 0; k < 32; k += 4) {
            float4 w1v = *(const float4*)(w1p + k0 + k);
            float4 w2v = *(const float4*)(w2p + k0 + k);
            acc1 += rs[b][k] * w1v.x + rs[b][k + 1] * w1v.y
                  + rs[b][k + 2] * w1v.z + rs[b][k + 3] * w1v.w;
            acc2 += hs[b][k] * w2v.x + hs[b][k + 1] * w2v.y
                  + hs[b][k + 2] * w2v.z + hs[b][k + 3] * w2v.w;
        }
        __syncthreads();
    }
    g_rep[b * kH + j] = ftanh(acc1 + b1[j] + acc2 + b2[j]);
}

// ---------------- final: out = rep@fc3^T + b3 ----------
__global__ void final_out_k(const float* __restrict__ fc3w,
                            const float* __restrict__ fc3b, float* __restrict__ out)
{
    int b = blockIdx.x, c = blockIdx.y, lane = threadIdx.x;
    float acc = 0.f;
    for (int k = lane; k < kH; k += 32)
        acc += g_rep[b * kH + k] * fc3w[c * kH + k];
#pragma unroll
    for (int o = 16; o; o >>= 1) acc += __shfl_xor_sync(0xffffffffu, acc, o);
    if (lane == 0) out[b * kC + c] = acc + fc3b[c];
}

// ---------------- launch ----------------
extern "C" void kernel_launch(void* const* d_in, const int* in_sizes, int n_in,
                              void* d_out, int out_size)
{
    // -------- strict size-based binding (E = 300!) --------
    const void *p_tokP, *p_tokH, *p_emb, *p_fc3w, *p_fc3b;
    const void *wih[2], *whh[2], *bia[4], *sq[6], *v512[3];
    int nwih, nwhh, nbia, nsq, nv;

    auto try_bind = [&](long long mult) -> bool {
        p_tokP = p_tokH = p_emb = p_fc3w = p_fc3b = 0;
        nwih = nwhh = nbia = nsq = nv = 0;
        for (int i = 0; i < 2; i++) { wih[i] = 0; whh[i] = 0; }
        for (int i = 0; i < 4; i++) bia[i] = 0;
        for (int i = 0; i < 6; i++) sq[i] = 0;
        for (int i = 0; i < 3; i++) v512[i] = 0;
        bool over = false;
        for (int i = 0; i < n_in; i++) {
            long long s = (long long)in_sizes[i];
            const void* p = d_in[i];
            if      (s == (long long)kB * kPL * mult)  { if (p_tokP) over = true; p_tokP = p; }
            else if (s == (long long)kB * kHL * mult)  { if (p_tokH) over = true; p_tokH = p; }
            else if (s == (long long)kV * kE * mult)   { if (p_emb)  over = true; p_emb  = p; }
            else if (s == (long long)kH4 * kE * mult)  { if (nwih < 2) wih[nwih++] = p; else over = true; }
            else if (s == (long long)kH4 * kH * mult)  { if (nwhh < 2) whh[nwhh++] = p; else over = true; }
            else if (s == (long long)kH4 * mult)       { if (nbia < 4) bia[nbia++] = p; else over = true; }
            else if (s == (long long)kH * kH * mult)   { if (nsq  < 6) sq [nsq++]  = p; else over = true; }
            else if (s == (long long)kH * mult)        { if (nv   < 3) v512[nv++]  = p; else over = true; }
            else if (s == (long long)kC * kH * mult)   { if (p_fc3w) over = true; p_fc3w = p; }
            else if (s == (long long)kC * mult)        { if (p_fc3b) over = true; p_fc3b = p; }
        }
        return !over && p_tokP && p_tokH && p_emb && p_fc3w && p_fc3b &&
               nwih == 2 && nwhh == 2 && nbia == 4 && nsq == 6 && nv == 3;
    };

    bool ok = try_bind(1);          // in_sizes as element counts
    if (!ok) ok = try_bind(4);      // in_sizes as byte counts
    if (!ok && n_in >= 22) {
        // positional fallback (setup_inputs dict order)
        p_tokP = d_in[0];  p_tokH = d_in[1];  p_emb = d_in[2];
        wih[0] = d_in[3];  whh[0] = d_in[4];  bia[0] = d_in[5];  bia[1] = d_in[6];
        wih[1] = d_in[7];  whh[1] = d_in[8];  bia[2] = d_in[9];  bia[3] = d_in[10];
        sq[0]  = d_in[11]; sq[1]  = d_in[12]; sq[2]  = d_in[13]; sq[3] = d_in[14];
        v512[0]= d_in[15];
        sq[4]  = d_in[16]; v512[1]= d_in[17];
        sq[5]  = d_in[18]; v512[2]= d_in[19];
        p_fc3w = d_in[20]; p_fc3b = d_in[21];
        ok = true;
    }
    if (!ok) {   // cannot bind: emit zeros rather than crash
        int n = out_size / 4;  if (n < 1) n = 1;
        zero_out_k<<<(n + 255) / 256, 256>>>((float*)d_out, n);
        return;
    }

    const int*   premise = (const int*)p_tokP;
    const int*   hyp     = (const int*)p_tokH;
    const float* emb     = (const float*)p_emb;
    const float* Wih1 = (const float*)wih[0]; const float* Whh1 = (const float*)whh[0];
    const float* Wih2 = (const float*)wih[1]; const float* Whh2 = (const float*)whh[1];
    const float* bih1 = (const float*)bia[0]; const float* bhh1 = (const float*)bia[1];
    const float* bih2 = (const float*)bia[2]; const float* bhh2 = (const float*)bia[3];
    const float* W_y  = (const float*)sq[0];  const float* W_h  = (const float*)sq[1];
    const float* W_r  = (const float*)sq[2];  const float* W_t  = (const float*)sq[3];
    const float* fc1_w= (const float*)sq[4];  const float* fc2_w= (const float*)sq[5];
    const float* w_att= (const float*)v512[0];
    const float* fc1_b= (const float*)v512[1];const float* fc2_b= (const float*)v512[2];
    const float* fc3_w= (const float*)p_fc3w; const float* fc3_b= (const float*)p_fc3b;
    float* out = (float*)d_out;

    // h0 = c0 = r = 0
    zero_init<<<128, 256>>>();

    // hoisted input projections (gather fused), K = E = 300
    dim3 blk(32, 32);
    dim3 gP(kH4 / 32, (kPL * kB) / 32);     // (64, 256)
    gemm_simple<<<gP, blk>>>(0, emb, premise, Wih1, bih1, bhh1, kH4, kE, kPL);
    dim3 gHyp(kH4 / 32, (kHL * kB) / 32);   // (64, 128)
    gemm_simple<<<gHyp, blk>>>(1, emb, hyp, Wih2, bih2, bhh2, kH4, kE, kHL);

    // premise LSTM scan
    for (int t = 0; t < kPL; t++)
        lstm_step<<<256, 128>>>(0, t, Whh1);

    // a1 = out_p @ W_y^T  (K = H = 512)
    dim3 gA1(kH / 32, (kB * kPL) / 32);     // (16, 256)
    gemm_simple<<<gA1, blk>>>(2, nullptr, nullptr, W_y, nullptr, nullptr, kH, kH, 0);

    // hypothesis LSTM: h0 = 0, c0 = c_p (in g_c[0] after 128 premise steps)
    zero_h0<<<128, 256>>>();
    for (int t = 0; t < kHL; t++)
        lstm_step<<<256, 128>>>(1, t, Whh2);

    // word-by-word attention scan
    for (int t = 0; t < kHL; t++) {
        att_pre<<<256, 128>>>(t, W_h, W_r, W_t);
        att_update<<<kB, 512>>>(w_att);
    }

    // classifier head (hn_h is in g_h[0] after 64 hyp steps)
    final_rep<<<256, 128>>>(fc1_w, fc1_b, fc2_w, fc2_b);
    dim3 gO(kB, kC);
    final_out_k<<<gO, 32>>>(fc3_w, fc3_b, out);
}

// round 9
// speedup vs baseline: 1.3579x; 1.3579x over previous
#include <cuda_runtime.h>
#include <math.h>

// Problem dims (V,E,H,C = 50000,300,512,3; B=64,P=128,Th=64)
#define kB   64
#define kE   300
#define kH   512
#define kH4  2048
#define kPL  128
#define kHL  64
#define kC   3
#define kV   50000

// ---------------- scratch ----------------
__device__ __align__(16) float g_GXp[(size_t)kPL*kB*kH4];
__device__ __align__(16) float g_GXh[(size_t)kHL*kB*kH4];
__device__ __align__(16) float g_outp[(size_t)kB*kPL*kH];
__device__ __align__(16) float g_outh[(size_t)kB*kHL*kH];
__device__ __align__(16) float g_a1  [(size_t)kB*kPL*kH];
__device__ __align__(16) float g_gates[(size_t)kB*kH4];
__device__ __align__(16) float g_h[2][kB*kH];
__device__ __align__(16) float g_c[2][kB*kH];
__device__ __align__(16) float g_r  [kB*kH];
__device__ __align__(16) float g_a2 [kB*kH];
__device__ __align__(16) float g_rt [kB*kH];
__device__ __align__(16) float g_rep[kB*kH];

__device__ __forceinline__ float fsigmoid(float x) {
    return __fdividef(1.0f, 1.0f + __expf(-x));
}
__device__ __forceinline__ float ftanh(float x) {
    return 1.0f - __fdividef(2.0f, __expf(2.0f * x) + 1.0f);
}

// ---------------- utility ----------------
__global__ void zero_init() {
    int i = blockIdx.x * blockDim.x + threadIdx.x;
    if (i < kB * kH) { g_h[0][i] = 0.f; g_c[0][i] = 0.f; g_r[i] = 0.f; }
}
__global__ void zero_h0() {
    int i = blockIdx.x * blockDim.x + threadIdx.x;
    if (i < kB * kH) g_h[0][i] = 0.f;
}
__global__ void zero_out_k(float* out, int n) {
    int i = blockIdx.x * blockDim.x + threadIdx.x;
    if (i < n) out[i] = 0.f;
}

// ---------------- GEMM 64x64 tile, 4x4 microtile, 256 threads -------------
// C[m][n] = bias(n) + sum_k A(m,k) * W[n][k]
// mode 0: A = emb[premise gather] (K=300) -> g_GXp
// mode 1: A = emb[hyp gather]     (K=300) -> g_GXh
// mode 2: A = g_outp              (K=512) -> g_a1
__global__ void __launch_bounds__(256) gemm64(
    int mode, const float* __restrict__ emb, const int* __restrict__ tok,
    const float* __restrict__ W, const float* __restrict__ bias1,
    const float* __restrict__ bias2, int N, int K, int T)
{
    float* Cout = (mode == 0) ? g_GXp : (mode == 1) ? g_GXh : g_a1;

    __shared__ __align__(16) float As[32][68];
    __shared__ __align__(16) float Ws[32][68];

    int tid = threadIdx.x;
    int m0 = blockIdx.y * 64, n0 = blockIdx.x * 64;

    // loader role: row lr (0..63), k-offset group lks in {0,8,16,24}
    int lr  = tid & 63;
    int lks = (tid >> 6) << 3;

    const float* arow;
    if (mode <= 1) {
        int m = m0 + lr;
        int tt = m >> 6;              // m / kB
        int bb = m & 63;              // m % kB
        int tk = tok[bb * T + tt];
        tk = (tk < 0) ? 0 : ((tk >= kV) ? (kV - 1) : tk);
        arow = emb + (size_t)tk * K;
    } else {
        arow = g_outp + (size_t)(m0 + lr) * K;
    }
    const float* wrow = W + (size_t)(n0 + lr) * K;

    int tx = tid & 15, ty = tid >> 4;   // 16x16 compute layout
    float acc[4][4] = {};

    for (int k0 = 0; k0 < K; k0 += 32) {
        __syncthreads();
#pragma unroll
        for (int kk2 = 0; kk2 < 8; kk2++) {
            int k = k0 + lks + kk2;
            As[lks + kk2][lr] = (k < K) ? arow[k] : 0.f;
            Ws[lks + kk2][lr] = (k < K) ? wrow[k] : 0.f;
        }
        __syncthreads();
#pragma unroll
        for (int kk = 0; kk < 32; kk++) {
            float4 a = *(const float4*)&As[kk][ty << 2];
            float4 w = *(const float4*)&Ws[kk][tx << 2];
            acc[0][0] += a.x * w.x; acc[0][1] += a.x * w.y;
            acc[0][2] += a.x * w.z; acc[0][3] += a.x * w.w;
            acc[1][0] += a.y * w.x; acc[1][1] += a.y * w.y;
            acc[1][2] += a.y * w.z; acc[1][3] += a.y * w.w;
            acc[2][0] += a.z * w.x; acc[2][1] += a.z * w.y;
            acc[2][2] += a.z * w.z; acc[2][3] += a.z * w.w;
            acc[3][0] += a.w * w.x; acc[3][1] += a.w * w.y;
            acc[3][2] += a.w * w.z; acc[3][3] += a.w * w.w;
        }
    }
#pragma unroll
    for (int i = 0; i < 4; i++) {
        int m = m0 + (ty << 2) + i;
        float* crow = Cout + (size_t)m * N + n0 + (tx << 2);
#pragma unroll
        for (int j = 0; j < 4; j++) {
            float v = acc[i][j];
            int n = n0 + (tx << 2) + j;
            if (bias1) v += bias1[n];
            if (bias2) v += bias2[n];
            crow[j] = v;
        }
    }
}

// ---------------- LSTM phase A: gate preactivations (GEMM) -----------------
// G[b][n] = GX[t][b][n] + sum_k h[b][k] * Whh[n][k]
// grid 512 blocks x 256 thr. thread = (b = tid&63, n = blk*4 + tid>>6)
__global__ void __launch_bounds__(256) lstm_gemm(
    int phase, int t, const float* __restrict__ Whh)
{
    const float* GX = (phase == 0) ? g_GXp + (size_t)t * kB * kH4
                                   : g_GXh + (size_t)t * kB * kH4;
    const float* h_in = g_h[t & 1];

    __shared__ __align__(16) float hs[64][68];
    int tid = threadIdx.x;
    int b = tid & 63;
    int n = (blockIdx.x << 2) + (tid >> 6);
    const float* wrow = Whh + (size_t)n * kH;

    float a0 = 0.f, a1 = 0.f, a2 = 0.f, a3 = 0.f;
    for (int k0 = 0; k0 < kH; k0 += 64) {
        __syncthreads();
#pragma unroll
        for (int i = 0; i < 4; i++) {
            int l = tid + (i << 8);        // 0..1023 float4-groups
            int row = l >> 4;              // 0..63
            int c4 = (l & 15) << 2;        // 0..60
            *(float4*)&hs[row][c4] = *(const float4*)(h_in + row * kH + k0 + c4);
        }
        __syncthreads();
#pragma unroll
        for (int kk = 0; kk < 64; kk += 4) {
            float4 hv = *(const float4*)&hs[b][kk];
            float4 wv = *(const float4*)(wrow + k0 + kk);
            a0 += hv.x * wv.x; a1 += hv.y * wv.y;
            a2 += hv.z * wv.z; a3 += hv.w * wv.w;
        }
    }
    g_gates[b * kH4 + n] = GX[b * kH4 + n] + ((a0 + a1) + (a2 + a3));
}

// ---------------- LSTM phase B: gate nonlinearity + state update -----------
// grid 128 x 256. i = b*512 + j
__global__ void __launch_bounds__(256) lstm_point(int phase, int t)
{
    int i = blockIdx.x * 256 + threadIdx.x;   // 0..32767
    int b = i >> 9, j = i & 511;
    float* outbuf; int T;
    if (phase == 0) { outbuf = g_outp; T = kPL; }
    else            { outbuf = g_outh; T = kHL; }
    const float* c_in = g_c[t & 1];
    float* h_out = g_h[(t + 1) & 1];
    float* c_out = g_c[(t + 1) & 1];

    float gi = g_gates[b * kH4 + j];
    float gf = g_gates[b * kH4 + 512 + j];
    float gg = g_gates[b * kH4 + 1024 + j];
    float go = g_gates[b * kH4 + 1536 + j];
    float c = fsigmoid(gf) * c_in[i] + fsigmoid(gi) * ftanh(gg);
    float h = fsigmoid(go) * ftanh(c);
    c_out[i] = c;
    h_out[i] = h;
    outbuf[((size_t)b * T + t) * kH + j] = h;
}

// ---------------- attention precompute (fused 3 GEMVs, high occupancy) -----
// rows n in [0,512):  a2[b][n] = q.Wh[n] + r.Wr[n]
// rows n in [512,1024): rt[b][n-512] = tanh(r.Wt[n-512])
// grid 256 x 256 thr. thread = (b = tid&63, n = blk*4 + tid>>6)
__global__ void __launch_bounds__(256) att_pre2(
    int t, const float* __restrict__ Wh, const float* __restrict__ Wr,
    const float* __restrict__ Wt)
{
    __shared__ __align__(16) float qs[64][68];
    __shared__ __align__(16) float rs[64][68];
    int tid = threadIdx.x;
    int b = tid & 63;
    int n = (blockIdx.x << 2) + (tid >> 6);
    bool isA = (n < 512);                 // uniform per block (4 | 512)

    const float* w1 = isA ? (Wh + (size_t)n * kH) : (Wt + (size_t)(n - 512) * kH);
    const float* w2 = Wr + (size_t)(isA ? n : 0) * kH;

    float acc1 = 0.f, acc2 = 0.f;
    for (int k0 = 0; k0 < kH; k0 += 64) {
        __syncthreads();
#pragma unroll
        for (int i = 0; i < 4; i++) {
            int l = tid + (i << 8);
            int row = l >> 4;
            int c4 = (l & 15) << 2;
            *(float4*)&rs[row][c4] = *(const float4*)(g_r + row * kH + k0 + c4);
            if (isA)
                *(float4*)&qs[row][c4] =
                    *(const float4*)(g_outh + ((size_t)row * kHL + t) * kH + k0 + c4);
        }
        __syncthreads();
#pragma unroll
        for (int kk = 0; kk < 64; kk += 4) {
            float4 w1v = *(const float4*)(w1 + k0 + kk);
            float4 rv  = *(const float4*)&rs[b][kk];
            if (isA) {
                float4 w2v = *(const float4*)(w2 + k0 + kk);
                float4 qv  = *(const float4*)&qs[b][kk];
                acc1 += qv.x * w1v.x + qv.y * w1v.y + qv.z * w1v.z + qv.w * w1v.w;
                acc2 += rv.x * w2v.x + rv.y * w2v.y + rv.z * w2v.z + rv.w * w2v.w;
            } else {
                acc1 += rv.x * w1v.x + rv.y * w1v.y + rv.z * w1v.z + rv.w * w1v.w;
            }
        }
    }
    if (isA) g_a2[b * kH + n] = acc1 + acc2;
    else     g_rt[b * kH + (n - 512)] = ftanh(acc1);
}

// ---------------- attention scores + softmax + r update (one block per b) --
__global__ void __launch_bounds__(512) att_update(const float* __restrict__ w_att)
{
    int b = blockIdx.x;
    int tid = threadIdx.x;
    __shared__ float a2s[512];
    __shared__ float wvs[512];
    __shared__ float ss[128];
    __shared__ float red[16];

    a2s[tid] = g_a2[b * kH + tid];
    wvs[tid] = w_att[tid];
    __syncthreads();

    int p = tid >> 2, sub = tid & 3;
    const float* a1p = g_a1 + ((size_t)b * kPL + p) * kH + (sub << 7);
    const float* a2p = a2s + (sub << 7);
    const float* wvp = wvs + (sub << 7);
    float part = 0.f;
#pragma unroll 4
    for (int k = 0; k < 128; k++)
        part += wvp[k] * ftanh(a1p[k] + a2p[k]);
    part += __shfl_xor_sync(0xffffffffu, part, 1);
    part += __shfl_xor_sync(0xffffffffu, part, 2);
    if (sub == 0) ss[p] = part;
    __syncthreads();

    float v = (tid < 128) ? ss[tid] : -3.4e38f;
#pragma unroll
    for (int o = 16; o; o >>= 1) v = fmaxf(v, __shfl_xor_sync(0xffffffffu, v, o));
    if ((tid & 31) == 0) red[tid >> 5] = v;
    __syncthreads();
    float mx = red[0];
#pragma unroll
    for (int w = 1; w < 16; w++) mx = fmaxf(mx, red[w]);
    __syncthreads();

    float e = 0.f;
    if (tid < 128) e = __expf(ss[tid] - mx);
    float sv = e;
#pragma unroll
    for (int o = 16; o; o >>= 1) sv += __shfl_xor_sync(0xffffffffu, sv, o);
    if ((tid & 31) == 0) red[tid >> 5] = sv;
    __syncthreads();
    float tot = 0.f;
#pragma unroll
    for (int w = 0; w < 16; w++) tot += red[w];
    if (tid < 128) ss[tid] = __fdividef(e, tot);
    __syncthreads();

    float acc = g_rt[b * kH + tid];
    const float* op = g_outp + (size_t)b * kPL * kH + tid;
#pragma unroll 4
    for (int p2 = 0; p2 < kPL; p2++)
        acc += op[(size_t)p2 * kH] * ss[p2];
    g_r[b * kH + tid] = acc;
}

// ---------------- final: rep = tanh(r@fc1^T + b1 + hn@fc2^T + b2) ----------
__global__ void __launch_bounds__(128) final_rep(
    const float* __restrict__ w1, const float* __restrict__ b1,
    const float* __restrict__ w2, const float* __restrict__ b2)
{
    __shared__ float rs[64][33];
    __shared__ float hs[64][33];
    int tid = threadIdx.x;
    int b = tid & 63;
    int j = (blockIdx.x << 1) + (tid >> 6);
    const float* hn = g_h[0];

    float acc1 = 0.f, acc2 = 0.f;
    const float* w1p = w1 + (size_t)j * kH;
    const float* w2p = w2 + (size_t)j * kH;

    for (int k0 = 0; k0 < kH; k0 += 32) {
#pragma unroll
        for (int i = 0; i < 4; i++) {
            int l = i * 128 + tid;
            int row = l >> 3;
            int c4 = (l & 7) << 2;
            float4 rv = *(const float4*)(g_r + row * kH + k0 + c4);
            float4 hv = *(const float4*)(hn + row * kH + k0 + c4);
            rs[row][c4 + 0] = rv.x; rs[row][c4 + 1] = rv.y;
            rs[row][c4 + 2] = rv.z; rs[row][c4 + 3] = rv.w;
            hs[row][c4 + 0] = hv.x; hs[row][c4 + 1] = hv.y;
            hs[row][c4 + 2] = hv.z; hs[row][c4 + 3] = hv.w;
        }
        __syncthreads();
#pragma unroll
        for (int k = 0; k < 32; k += 4) {
            float4 w1v = *(const float4*)(w1p + k0 + k);
            float4 w2v = *(const float4*)(w2p + k0 + k);
            acc1 += rs[b][k] * w1v.x + rs[b][k + 1] * w1v.y
                  + rs[b][k + 2] * w1v.z + rs[b][k + 3] * w1v.w;
            acc2 += hs[b][k] * w2v.x + hs[b][k + 1] * w2v.y
                  + hs[b][k + 2] * w2v.z + hs[b][k + 3] * w2v.w;
        }
        __syncthreads();
    }
    g_rep[b * kH + j] = ftanh(acc1 + b1[j] + acc2 + b2[j]);
}

// ---------------- final: out = rep@fc3^T + b3 ----------
__global__ void final_out_k(const float* __restrict__ fc3w,
                            const float* __restrict__ fc3b, float* __restrict__ out)
{
    int b = blockIdx.x, c = blockIdx.y, lane = threadIdx.x;
    float acc = 0.f;
    for (int k = lane; k < kH; k += 32)
        acc += g_rep[b * kH + k] * fc3w[c * kH + k];
#pragma unroll
    for (int o = 16; o; o >>= 1) acc += __shfl_xor_sync(0xffffffffu, acc, o);
    if (lane == 0) out[b * kC + c] = acc + fc3b[c];
}

// ---------------- launch ----------------
extern "C" void kernel_launch(void* const* d_in, const int* in_sizes, int n_in,
                              void* d_out, int out_size)
{
    const void *p_tokP, *p_tokH, *p_emb, *p_fc3w, *p_fc3b;
    const void *wih[2], *whh[2], *bia[4], *sq[6], *v512[3];
    int nwih, nwhh, nbia, nsq, nv;

    auto try_bind = [&](long long mult) -> bool {
        p_tokP = p_tokH = p_emb = p_fc3w = p_fc3b = 0;
        nwih = nwhh = nbia = nsq = nv = 0;
        for (int i = 0; i < 2; i++) { wih[i] = 0; whh[i] = 0; }
        for (int i = 0; i < 4; i++) bia[i] = 0;
        for (int i = 0; i < 6; i++) sq[i] = 0;
        for (int i = 0; i < 3; i++) v512[i] = 0;
        bool over = false;
        for (int i = 0; i < n_in; i++) {
            long long s = (long long)in_sizes[i];
            const void* p = d_in[i];
            if      (s == (long long)kB * kPL * mult)  { if (p_tokP) over = true; p_tokP = p; }
            else if (s == (long long)kB * kHL * mult)  { if (p_tokH) over = true; p_tokH = p; }
            else if (s == (long long)kV * kE * mult)   { if (p_emb)  over = true; p_emb  = p; }
            else if (s == (long long)kH4 * kE * mult)  { if (nwih < 2) wih[nwih++] = p; else over = true; }
            else if (s == (long long)kH4 * kH * mult)  { if (nwhh < 2) whh[nwhh++] = p; else over = true; }
            else if (s == (long long)kH4 * mult)       { if (nbia < 4) bia[nbia++] = p; else over = true; }
            else if (s == (long long)kH * kH * mult)   { if (nsq  < 6) sq [nsq++]  = p; else over = true; }
            else if (s == (long long)kH * mult)        { if (nv   < 3) v512[nv++]  = p; else over = true; }
            else if (s == (long long)kC * kH * mult)   { if (p_fc3w) over = true; p_fc3w = p; }
            else if (s == (long long)kC * mult)        { if (p_fc3b) over = true; p_fc3b = p; }
        }
        return !over && p_tokP && p_tokH && p_emb && p_fc3w && p_fc3b &&
               nwih == 2 && nwhh == 2 && nbia == 4 && nsq == 6 && nv == 3;
    };

    bool ok = try_bind(1);
    if (!ok) ok = try_bind(4);
    if (!ok && n_in >= 22) {
        p_tokP = d_in[0];  p_tokH = d_in[1];  p_emb = d_in[2];
        wih[0] = d_in[3];  whh[0] = d_in[4];  bia[0] = d_in[5];  bia[1] = d_in[6];
        wih[1] = d_in[7];  whh[1] = d_in[8];  bia[2] = d_in[9];  bia[3] = d_in[10];
        sq[0]  = d_in[11]; sq[1]  = d_in[12]; sq[2]  = d_in[13]; sq[3] = d_in[14];
        v512[0]= d_in[15];
        sq[4]  = d_in[16]; v512[1]= d_in[17];
        sq[5]  = d_in[18]; v512[2]= d_in[19];
        p_fc3w = d_in[20]; p_fc3b = d_in[21];
        ok = true;
    }
    if (!ok) {
        int n = out_size / 4;  if (n < 1) n = 1;
        zero_out_k<<<(n + 255) / 256, 256>>>((float*)d_out, n);
        return;
    }

    const int*   premise = (const int*)p_tokP;
    const int*   hyp     = (const int*)p_tokH;
    const float* emb     = (const float*)p_emb;
    const float* Wih1 = (const float*)wih[0]; const float* Whh1 = (const float*)whh[0];
    const float* Wih2 = (const float*)wih[1]; const float* Whh2 = (const float*)whh[1];
    const float* bih1 = (const float*)bia[0]; const float* bhh1 = (const float*)bia[1];
    const float* bih2 = (const float*)bia[2]; const float* bhh2 = (const float*)bia[3];
    const float* W_y  = (const float*)sq[0];  const float* W_h  = (const float*)sq[1];
    const float* W_r  = (const float*)sq[2];  const float* W_t  = (const float*)sq[3];
    const float* fc1_w= (const float*)sq[4];  const float* fc2_w= (const float*)sq[5];
    const float* w_att= (const float*)v512[0];
    const float* fc1_b= (const float*)v512[1];const float* fc2_b= (const float*)v512[2];
    const float* fc3_w= (const float*)p_fc3w; const float* fc3_b= (const float*)p_fc3b;
    float* out = (float*)d_out;

    zero_init<<<128, 256>>>();

    // hoisted input projections (gather fused), K = E = 300
    dim3 gP(kH4 / 64, (kPL * kB) / 64);     // (32, 128)
    gemm64<<<gP, 256>>>(0, emb, premise, Wih1, bih1, bhh1, kH4, kE, kPL);
    dim3 gHyp(kH4 / 64, (kHL * kB) / 64);   // (32, 64)
    gemm64<<<gHyp, 256>>>(1, emb, hyp, Wih2, bih2, bhh2, kH4, kE, kHL);

    // premise LSTM scan (two-phase per step)
    for (int t = 0; t < kPL; t++) {
        lstm_gemm<<<512, 256>>>(0, t, Whh1);
        lstm_point<<<128, 256>>>(0, t);
    }

    // a1 = out_p @ W_y^T  (K = H = 512)
    dim3 gA1(kH / 64, (kB * kPL) / 64);     // (8, 128)
    gemm64<<<gA1, 256>>>(2, nullptr, nullptr, W_y, nullptr, nullptr, kH, kH, 0);

    // hypothesis LSTM: h0 = 0, c0 = c_p (in g_c[0] after 128 premise steps)
    zero_h0<<<128, 256>>>();
    for (int t = 0; t < kHL; t++) {
        lstm_gemm<<<512, 256>>>(1, t, Whh2);
        lstm_point<<<128, 256>>>(1, t);
    }

    // word-by-word attention scan
    for (int t = 0; t < kHL; t++) {
        att_pre2<<<256, 256>>>(t, W_h, W_r, W_t);
        att_update<<<kB, 512>>>(w_att);
    }

    // classifier head (hn_h in g_h[0] after 64 hyp steps)
    final_rep<<<256, 128>>>(fc1_w, fc1_b, fc2_w, fc2_b);
    dim3 gO(kB, kC);
    final_out_k<<<gO, 32>>>(fc3_w, fc3_b, out);
}